// round 5
// baseline (speedup 1.0000x reference)
#include <cuda_runtime.h>
#include <cstdint>

#define HH    56
#define WW    56
#define HWSZ  3136            // 56*56
#define NPIX  50176           // 16*3136
#define XSTRB 401408          // 128*3136
#define NELEM 6422528         // 16*128*56*56

// ---------------- device scratch ----------------
__device__ float g_wq1[9 * 128 * 128];   // quantized weights [k][c][o]
__device__ float g_wq2[9 * 128 * 128];
__device__ float g_t0 [128 * NPIX];      // x transposed to [c][n]
__device__ float g_t1 [128 * NPIX];      // conv1 pre-BN output [c][n]
__device__ float g_t1r[128 * NPIX];      // relu(bn1(t1)) [c][n]
__device__ float g_t2 [128 * NPIX];      // conv2 pre-BN output [c][n]
__device__ float g_sum1[128], g_sumsq1[128];
__device__ float g_sum2[128], g_sumsq2[128];
__device__ float g_scale1[128], g_bias1[128];
__device__ float g_scale2[128], g_bias2[128];

// ---------------- f32x2 packed helpers (sm_103a) ----------------
static __device__ __forceinline__ uint64_t pack2(float a, float b) {
    uint64_t r; asm("mov.b64 %0,{%1,%2};" : "=l"(r) : "f"(a), "f"(b)); return r;
}
static __device__ __forceinline__ void unpack2(uint64_t v, float& a, float& b) {
    asm("mov.b64 {%0,%1},%2;" : "=f"(a), "=f"(b) : "l"(v));
}
static __device__ __forceinline__ uint64_t fma2(uint64_t a, uint64_t b, uint64_t c) {
    uint64_t d; asm("fma.rn.f32x2 %0,%1,%2,%3;" : "=l"(d) : "l"(a), "l"(b), "l"(c)); return d;
}

// ---------------- prep: quantize weights (LSQ 3-bit) + zero stats ----------------
__global__ void prep_kernel(const float* __restrict__ w1, const float* __restrict__ wa1,
                            const float* __restrict__ w2, const float* __restrict__ wa2)
{
    if (blockIdx.x == 0 && threadIdx.x < 128) {
        int t = threadIdx.x;
        g_sum1[t] = 0.f; g_sumsq1[t] = 0.f;
        g_sum2[t] = 0.f; g_sumsq2[t] = 0.f;
    }
    int idx = blockIdx.x * blockDim.x + threadIdx.x;
    if (idx < 2 * 9 * 128 * 128) {
        int layer = idx / (9 * 128 * 128);
        int r = idx - layer * (9 * 128 * 128);
        int k = r >> 14;
        int o = (r >> 7) & 127;
        int c = r & 127;
        const float* w  = layer ? w2  : w1;
        const float* wa = layer ? wa2 : wa1;
        float alpha = wa[k];
        float v = __fdiv_rn(w[(k << 14) + (o << 7) + c], alpha);
        v = fminf(fmaxf(v, -4.f), 3.f);
        float q = __fmul_rn(rintf(v), alpha);
        float* dst = layer ? g_wq2 : g_wq1;
        dst[(k << 14) + (c << 7) + o] = q;   // [k][c][o]
    }
}

// ---------------- transpose x: NCHW -> [c][n] ----------------
__global__ void transpose_x_kernel(const float* __restrict__ x)
{
    int bc = blockIdx.x;            // 16*128 planes
    int b = bc >> 7;
    int c = bc & 127;
    const float4* src = reinterpret_cast<const float4*>(x + b * XSTRB + c * HWSZ);
    float4* dst = reinterpret_cast<float4*>(g_t0 + c * NPIX + b * HWSZ);
    for (int i = threadIdx.x; i < HWSZ / 4; i += 256) dst[i] = src[i];
}

// ---------------- apply BN1 + ReLU: g_t1r = relu(bn1(g_t1)) ----------------
__global__ void bn_apply_kernel()
{
    int idx = blockIdx.x * 256 + threadIdx.x;   // float4 index over [c][n]
    if (idx >= NELEM / 4) return;
    int c = idx / (NPIX / 4);
    float s = g_scale1[c], bb = g_bias1[c];
    float4 v = reinterpret_cast<const float4*>(g_t1)[idx];
    v.x = fmaxf(fmaf(v.x, s, bb), 0.f);
    v.y = fmaxf(fmaf(v.y, s, bb), 0.f);
    v.z = fmaxf(fmaf(v.z, s, bb), 0.f);
    v.w = fmaxf(fmaf(v.w, s, bb), 0.f);
    reinterpret_cast<float4*>(g_t1r)[idx] = v;
}

// ---------------- conv: 9-tap split conv, psum LSQ(8b), f32x2 core ----------------
// Block tile: 64 n x 128 o. 256 threads, each 8o x 4n (o packed in f32x2 pairs).
template <int LAYER>
__global__ __launch_bounds__(256, 2)
void conv_kernel(const float* __restrict__ pa)
{
    __shared__ float sA[2][16][64];
    __shared__ float sB[2][16][128];
    __shared__ float sRed[2][128];

    const int t  = threadIdx.x;
    const int n0 = blockIdx.x << 6;
    const int nl = t & 63;
    const int nn = n0 + nl;
    const int b  = nn / HWSZ;
    const int hw = nn - b * HWSZ;
    const int h  = hw / WW;
    const int w  = hw - h * WW;
    const int caRow = t >> 6;       // 0..3
    const int og = t & 15;
    const int ng = t >> 4;
    const int bo = t & 127;
    const int bRow = t >> 7;        // 0..1

    const float* src = (LAYER == 1) ? g_t0  : g_t1r;
    const float* wq  = (LAYER == 1) ? g_wq1 : g_wq2;

    float ra[4];
    float rb[8];

    // ---- prefetch chunk q=0 (k=0: dh=-1, dw=-1) ----
    {
        const int hh = h - 1, ww2 = w - 1;
        const bool valid = (hh >= 0) && (ww2 >= 0);
        const int base = b * HWSZ + hh * WW + ww2;
#pragma unroll
        for (int i = 0; i < 4; i++) {
            int c = caRow + (i << 2);
            ra[i] = valid ? __ldg(src + c * NPIX + base) : 0.f;
        }
#pragma unroll
        for (int i = 0; i < 8; i++)
            rb[i] = __ldg(wq + ((bRow + (i << 1)) << 7) + bo);
    }
#pragma unroll
    for (int i = 0; i < 4; i++) sA[0][caRow + (i << 2)][nl] = ra[i];
#pragma unroll
    for (int i = 0; i < 8; i++) sB[0][bRow + (i << 1)][bo] = rb[i];
    __syncthreads();

    uint64_t psum[4][4];
#pragma unroll
    for (int i = 0; i < 4; i++)
#pragma unroll
        for (int j = 0; j < 4; j++) psum[i][j] = 0ull;

    float acc[8][4];
#pragma unroll
    for (int i = 0; i < 8; i++)
#pragma unroll
        for (int j = 0; j < 4; j++) acc[i][j] = 0.f;

    float pak = __ldg(pa);

#pragma unroll 1
    for (int q = 0; q < 72; q++) {
        const int buf = q & 1;

        // prefetch next chunk into registers (overlapped with compute)
        if (q < 71) {
            const int q1  = q + 1;
            const int k1  = q1 >> 3;
            const int cc1 = (q1 & 7) << 4;
            const int dh = k1 % 3 - 1;
            const int dw = k1 / 3 - 1;
            const int hh = h + dh, ww2 = w + dw;
            const bool valid = (hh >= 0) && (hh < HH) && (ww2 >= 0) && (ww2 < WW);
            const int base = b * HWSZ + hh * WW + ww2;
#pragma unroll
            for (int i = 0; i < 4; i++) {
                int c = cc1 + caRow + (i << 2);
                ra[i] = valid ? __ldg(src + c * NPIX + base) : 0.f;
            }
            const float* wk = wq + (k1 << 14) + (cc1 << 7);
#pragma unroll
            for (int i = 0; i < 8; i++)
                rb[i] = __ldg(wk + ((bRow + (i << 1)) << 7) + bo);
        }

        // ---- f32x2 FMA core: 16 c-steps ----
#pragma unroll
        for (int c = 0; c < 16; c++) {
            float4 av = *reinterpret_cast<const float4*>(&sA[buf][c][ng << 2]);
            const ulonglong2* pb = reinterpret_cast<const ulonglong2*>(&sB[buf][c][og << 3]);
            ulonglong2 bv0 = pb[0];
            ulonglong2 bv1 = pb[1];
            uint64_t a0 = pack2(av.x, av.x);
            uint64_t a1 = pack2(av.y, av.y);
            uint64_t a2 = pack2(av.z, av.z);
            uint64_t a3 = pack2(av.w, av.w);
            psum[0][0] = fma2(a0, bv0.x, psum[0][0]);
            psum[0][1] = fma2(a1, bv0.x, psum[0][1]);
            psum[0][2] = fma2(a2, bv0.x, psum[0][2]);
            psum[0][3] = fma2(a3, bv0.x, psum[0][3]);
            psum[1][0] = fma2(a0, bv0.y, psum[1][0]);
            psum[1][1] = fma2(a1, bv0.y, psum[1][1]);
            psum[1][2] = fma2(a2, bv0.y, psum[1][2]);
            psum[1][3] = fma2(a3, bv0.y, psum[1][3]);
            psum[2][0] = fma2(a0, bv1.x, psum[2][0]);
            psum[2][1] = fma2(a1, bv1.x, psum[2][1]);
            psum[2][2] = fma2(a2, bv1.x, psum[2][2]);
            psum[2][3] = fma2(a3, bv1.x, psum[2][3]);
            psum[3][0] = fma2(a0, bv1.y, psum[3][0]);
            psum[3][1] = fma2(a1, bv1.y, psum[3][1]);
            psum[3][2] = fma2(a2, bv1.y, psum[3][2]);
            psum[3][3] = fma2(a3, bv1.y, psum[3][3]);
        }

        // ---- per-tap partial-sum LSQ at tap boundary ----
        if ((q & 7) == 7) {
#pragma unroll
            for (int i2 = 0; i2 < 4; i2++)
#pragma unroll
                for (int j = 0; j < 4; j++) {
                    float p0, p1;
                    unpack2(psum[i2][j], p0, p1);
                    float v0 = __fdiv_rn(p0, pak);
                    v0 = fminf(fmaxf(v0, -128.f), 127.f);
                    acc[(i2 << 1) + 0][j] = __fadd_rn(acc[(i2 << 1) + 0][j], __fmul_rn(rintf(v0), pak));
                    float v1 = __fdiv_rn(p1, pak);
                    v1 = fminf(fmaxf(v1, -128.f), 127.f);
                    acc[(i2 << 1) + 1][j] = __fadd_rn(acc[(i2 << 1) + 1][j], __fmul_rn(rintf(v1), pak));
                    psum[i2][j] = 0ull;
                }
            if (q < 71) pak = __ldg(pa + ((q + 1) >> 3));
        }

        // ---- store prefetched regs into other buffer ----
        if (q < 71) {
#pragma unroll
            for (int i = 0; i < 4; i++) sA[buf ^ 1][caRow + (i << 2)][nl] = ra[i];
#pragma unroll
            for (int i = 0; i < 8; i++) sB[buf ^ 1][bRow + (i << 1)][bo] = rb[i];
            __syncthreads();
        }
    }

    // ---------------- epilogue: stores [c][n] + per-channel BN stats ----------------
    float* outT = (LAYER == 1) ? g_t1 : g_t2;
    float* ssum = (LAYER == 1) ? g_sum1 : g_sum2;
    float* ssq  = (LAYER == 1) ? g_sumsq1 : g_sumsq2;

    if (t < 128) { sRed[0][t] = 0.f; sRed[1][t] = 0.f; }
    __syncthreads();

#pragma unroll
    for (int i = 0; i < 8; i++) {
        int o = (og << 3) + i;
        float4 vv = make_float4(acc[i][0], acc[i][1], acc[i][2], acc[i][3]);
        *reinterpret_cast<float4*>(&outT[o * NPIX + n0 + (ng << 2)]) = vv;
        float s = acc[i][0] + acc[i][1] + acc[i][2] + acc[i][3];
        float qs = acc[i][0] * acc[i][0] + acc[i][1] * acc[i][1] +
                   acc[i][2] * acc[i][2] + acc[i][3] * acc[i][3];
        atomicAdd(&sRed[0][o], s);
        atomicAdd(&sRed[1][o], qs);
    }
    __syncthreads();
    if (t < 128) {
        atomicAdd(&ssum[t], sRed[0][t]);
        atomicAdd(&ssq[t],  sRed[1][t]);
    }
}

// ---------------- BN finalize ----------------
__global__ void bn_finalize_kernel(int layer, const float* __restrict__ g, const float* __restrict__ bv)
{
    int c = threadIdx.x;
    if (c < 128) {
        float sum = (layer == 1) ? g_sum1[c]   : g_sum2[c];
        float sq  = (layer == 1) ? g_sumsq1[c] : g_sumsq2[c];
        float m   = __fdiv_rn(sum, (float)NPIX);
        float var = fmaxf(__fdiv_rn(sq, (float)NPIX) - m * m, 0.f);
        float s   = __fdiv_rn(g[c], sqrtf(var + 1e-5f));
        float bb  = bv[c] - m * s;
        if (layer == 1) { g_scale1[c] = s; g_bias1[c] = bb; }
        else            { g_scale2[c] = s; g_bias2[c] = bb; }
    }
}

// ---------------- final: out = relu(bn2(t2) + identity), NCHW ----------------
__global__ void final_kernel(const float* __restrict__ x, float* __restrict__ out)
{
    int idx = blockIdx.x * blockDim.x + threadIdx.x;   // float4 index
    if (idx >= NELEM / 4) return;
    int e  = idx << 2;
    int b  = e / XSTRB;
    int r  = e - b * XSTRB;
    int c  = r / HWSZ;
    int hw = r - c * HWSZ;
    float4 xv = *reinterpret_cast<const float4*>(x + e);
    float4 tv = *reinterpret_cast<const float4*>(&g_t2[c * NPIX + b * HWSZ + hw]);
    float s = g_scale2[c], bb = g_bias2[c];
    float4 ov;
    ov.x = fmaxf(fmaf(tv.x, s, bb) + xv.x, 0.f);
    ov.y = fmaxf(fmaf(tv.y, s, bb) + xv.y, 0.f);
    ov.z = fmaxf(fmaf(tv.z, s, bb) + xv.z, 0.f);
    ov.w = fmaxf(fmaf(tv.w, s, bb) + xv.w, 0.f);
    *reinterpret_cast<float4*>(out + e) = ov;
}

// ---------------- launch ----------------
extern "C" void kernel_launch(void* const* d_in, const int* in_sizes, int n_in,
                              void* d_out, int out_size)
{
    const float* x   = (const float*)d_in[0];
    const float* w1  = (const float*)d_in[1];
    const float* wa1 = (const float*)d_in[2];
    const float* pa1 = (const float*)d_in[3];
    const float* g1  = (const float*)d_in[4];
    const float* b1  = (const float*)d_in[5];
    const float* w2  = (const float*)d_in[6];
    const float* wa2 = (const float*)d_in[7];
    const float* pa2 = (const float*)d_in[8];
    const float* g2  = (const float*)d_in[9];
    const float* b2  = (const float*)d_in[10];
    float* out = (float*)d_out;

    (void)in_sizes; (void)n_in; (void)out_size;

    prep_kernel<<<1152, 256>>>(w1, wa1, w2, wa2);
    transpose_x_kernel<<<2048, 256>>>(x);
    conv_kernel<1><<<NPIX / 64, 256>>>(pa1);
    bn_finalize_kernel<<<1, 128>>>(1, g1, b1);
    bn_apply_kernel<<<NELEM / 4 / 256, 256>>>();
    conv_kernel<2><<<NPIX / 64, 256>>>(pa2);
    bn_finalize_kernel<<<1, 128>>>(2, g2, b2);
    final_kernel<<<NELEM / 4 / 256, 256>>>(x, out);
}

// round 6
// speedup vs baseline: 1.0018x; 1.0018x over previous
#include <cuda_runtime.h>
#include <cstdint>

#define HH    56
#define WW    56
#define HWSZ  3136            // 56*56
#define NPIX  50176           // 16*3136
#define XSTRB 401408          // 128*3136
#define NELEM 6422528         // 16*128*56*56

// ---------------- device scratch ----------------
__device__ float g_wq1[9 * 128 * 128];   // quantized weights [k][c][o]
__device__ float g_wq2[9 * 128 * 128];
__device__ float g_t0 [128 * NPIX];      // x transposed to [c][n]
__device__ float g_t1 [128 * NPIX];      // conv1 pre-BN output [c][n]
__device__ float g_t1r[128 * NPIX];      // relu(bn1(t1)) [c][n]
__device__ float g_t2 [128 * NPIX];      // conv2 pre-BN output [c][n]
__device__ float g_sum1[128], g_sumsq1[128];
__device__ float g_sum2[128], g_sumsq2[128];
__device__ float g_scale1[128], g_bias1[128];
__device__ float g_scale2[128], g_bias2[128];

// ---------------- f32x2 packed helpers (sm_103a) ----------------
static __device__ __forceinline__ uint64_t pack2(float a, float b) {
    uint64_t r; asm("mov.b64 %0,{%1,%2};" : "=l"(r) : "f"(a), "f"(b)); return r;
}
static __device__ __forceinline__ void unpack2(uint64_t v, float& a, float& b) {
    asm("mov.b64 {%0,%1},%2;" : "=f"(a), "=f"(b) : "l"(v));
}
static __device__ __forceinline__ uint64_t fma2(uint64_t a, uint64_t b, uint64_t c) {
    uint64_t d; asm("fma.rn.f32x2 %0,%1,%2,%3;" : "=l"(d) : "l"(a), "l"(b), "l"(c)); return d;
}

// ---------------- prep: quantize weights (LSQ 3-bit) + zero stats ----------------
__global__ void prep_kernel(const float* __restrict__ w1, const float* __restrict__ wa1,
                            const float* __restrict__ w2, const float* __restrict__ wa2)
{
    if (blockIdx.x == 0 && threadIdx.x < 128) {
        int t = threadIdx.x;
        g_sum1[t] = 0.f; g_sumsq1[t] = 0.f;
        g_sum2[t] = 0.f; g_sumsq2[t] = 0.f;
    }
    int idx = blockIdx.x * blockDim.x + threadIdx.x;
    if (idx < 2 * 9 * 128 * 128) {
        int layer = idx / (9 * 128 * 128);
        int r = idx - layer * (9 * 128 * 128);
        int k = r >> 14;
        int o = (r >> 7) & 127;
        int c = r & 127;
        const float* w  = layer ? w2  : w1;
        const float* wa = layer ? wa2 : wa1;
        float alpha = wa[k];
        float v = __fdiv_rn(w[(k << 14) + (o << 7) + c], alpha);
        v = fminf(fmaxf(v, -4.f), 3.f);
        float q = __fmul_rn(rintf(v), alpha);
        float* dst = layer ? g_wq2 : g_wq1;
        dst[(k << 14) + (c << 7) + o] = q;   // [k][c][o]
    }
}

// ---------------- transpose x: NCHW -> [c][n] ----------------
__global__ void transpose_x_kernel(const float* __restrict__ x)
{
    int bc = blockIdx.x;            // 16*128 planes
    int b = bc >> 7;
    int c = bc & 127;
    const float4* src = reinterpret_cast<const float4*>(x + b * XSTRB + c * HWSZ);
    float4* dst = reinterpret_cast<float4*>(g_t0 + c * NPIX + b * HWSZ);
    for (int i = threadIdx.x; i < HWSZ / 4; i += 256) dst[i] = src[i];
}

// ---------------- apply BN1 + ReLU: g_t1r = relu(bn1(g_t1)) ----------------
__global__ void bn_apply_kernel()
{
    int idx = blockIdx.x * 256 + threadIdx.x;   // float4 index over [c][n]
    if (idx >= NELEM / 4) return;
    int c = idx / (NPIX / 4);
    float s = g_scale1[c], bb = g_bias1[c];
    float4 v = reinterpret_cast<const float4*>(g_t1)[idx];
    v.x = fmaxf(fmaf(v.x, s, bb), 0.f);
    v.y = fmaxf(fmaf(v.y, s, bb), 0.f);
    v.z = fmaxf(fmaf(v.z, s, bb), 0.f);
    v.w = fmaxf(fmaf(v.w, s, bb), 0.f);
    reinterpret_cast<float4*>(g_t1r)[idx] = v;
}

// ---------------- conv: 9-tap split conv, psum LSQ(8b), f32x2 core ----------------
// Block tile: 64 n x 128 o. 256 threads, each 8o x 4n (o packed in f32x2 pairs).
template <int LAYER>
__global__ __launch_bounds__(256, 2)
void conv_kernel(const float* __restrict__ pa)
{
    __shared__ float sA[2][16][64];
    __shared__ float sB[2][16][128];
    __shared__ float sRed[2][128];

    const int t  = threadIdx.x;
    const int n0 = blockIdx.x << 6;
    const int nl = t & 63;
    const int nn = n0 + nl;
    const int b  = nn / HWSZ;
    const int hw = nn - b * HWSZ;
    const int h  = hw / WW;
    const int w  = hw - h * WW;
    const int caRow = t >> 6;       // 0..3
    const int og = t & 15;
    const int ng = t >> 4;
    const int bo = t & 127;
    const int bRow = t >> 7;        // 0..1

    const float* src = (LAYER == 1) ? g_t0  : g_t1r;
    const float* wq  = (LAYER == 1) ? g_wq1 : g_wq2;

    float ra[4];
    float rb[8];

    // ---- prefetch chunk q=0 (k=0: dh=-1, dw=-1) ----
    {
        const int hh = h - 1, ww2 = w - 1;
        const bool valid = (hh >= 0) && (ww2 >= 0);
        const int base = b * HWSZ + hh * WW + ww2;
#pragma unroll
        for (int i = 0; i < 4; i++) {
            int c = caRow + (i << 2);
            ra[i] = valid ? __ldg(src + c * NPIX + base) : 0.f;
        }
#pragma unroll
        for (int i = 0; i < 8; i++)
            rb[i] = __ldg(wq + ((bRow + (i << 1)) << 7) + bo);
    }
#pragma unroll
    for (int i = 0; i < 4; i++) sA[0][caRow + (i << 2)][nl] = ra[i];
#pragma unroll
    for (int i = 0; i < 8; i++) sB[0][bRow + (i << 1)][bo] = rb[i];
    __syncthreads();

    uint64_t psum[4][4];
#pragma unroll
    for (int i = 0; i < 4; i++)
#pragma unroll
        for (int j = 0; j < 4; j++) psum[i][j] = 0ull;

    float acc[8][4];
#pragma unroll
    for (int i = 0; i < 8; i++)
#pragma unroll
        for (int j = 0; j < 4; j++) acc[i][j] = 0.f;

    float pak = __ldg(pa);

#pragma unroll 1
    for (int q = 0; q < 72; q++) {
        const int buf = q & 1;

        // prefetch next chunk into registers (overlapped with compute)
        if (q < 71) {
            const int q1  = q + 1;
            const int k1  = q1 >> 3;
            const int cc1 = (q1 & 7) << 4;
            const int dh = k1 % 3 - 1;
            const int dw = k1 / 3 - 1;
            const int hh = h + dh, ww2 = w + dw;
            const bool valid = (hh >= 0) && (hh < HH) && (ww2 >= 0) && (ww2 < WW);
            const int base = b * HWSZ + hh * WW + ww2;
#pragma unroll
            for (int i = 0; i < 4; i++) {
                int c = cc1 + caRow + (i << 2);
                ra[i] = valid ? __ldg(src + c * NPIX + base) : 0.f;
            }
            const float* wk = wq + (k1 << 14) + (cc1 << 7);
#pragma unroll
            for (int i = 0; i < 8; i++)
                rb[i] = __ldg(wk + ((bRow + (i << 1)) << 7) + bo);
        }

        // ---- f32x2 FMA core: 16 c-steps ----
#pragma unroll
        for (int c = 0; c < 16; c++) {
            float4 av = *reinterpret_cast<const float4*>(&sA[buf][c][ng << 2]);
            const ulonglong2* pb = reinterpret_cast<const ulonglong2*>(&sB[buf][c][og << 3]);
            ulonglong2 bv0 = pb[0];
            ulonglong2 bv1 = pb[1];
            uint64_t a0 = pack2(av.x, av.x);
            uint64_t a1 = pack2(av.y, av.y);
            uint64_t a2 = pack2(av.z, av.z);
            uint64_t a3 = pack2(av.w, av.w);
            psum[0][0] = fma2(a0, bv0.x, psum[0][0]);
            psum[0][1] = fma2(a1, bv0.x, psum[0][1]);
            psum[0][2] = fma2(a2, bv0.x, psum[0][2]);
            psum[0][3] = fma2(a3, bv0.x, psum[0][3]);
            psum[1][0] = fma2(a0, bv0.y, psum[1][0]);
            psum[1][1] = fma2(a1, bv0.y, psum[1][1]);
            psum[1][2] = fma2(a2, bv0.y, psum[1][2]);
            psum[1][3] = fma2(a3, bv0.y, psum[1][3]);
            psum[2][0] = fma2(a0, bv1.x, psum[2][0]);
            psum[2][1] = fma2(a1, bv1.x, psum[2][1]);
            psum[2][2] = fma2(a2, bv1.x, psum[2][2]);
            psum[2][3] = fma2(a3, bv1.x, psum[2][3]);
            psum[3][0] = fma2(a0, bv1.y, psum[3][0]);
            psum[3][1] = fma2(a1, bv1.y, psum[3][1]);
            psum[3][2] = fma2(a2, bv1.y, psum[3][2]);
            psum[3][3] = fma2(a3, bv1.y, psum[3][3]);
        }

        // ---- per-tap partial-sum LSQ at tap boundary ----
        if ((q & 7) == 7) {
#pragma unroll
            for (int i2 = 0; i2 < 4; i2++)
#pragma unroll
                for (int j = 0; j < 4; j++) {
                    float p0, p1;
                    unpack2(psum[i2][j], p0, p1);
                    float v0 = __fdiv_rn(p0, pak);
                    v0 = fminf(fmaxf(v0, -128.f), 127.f);
                    acc[(i2 << 1) + 0][j] = __fadd_rn(acc[(i2 << 1) + 0][j], __fmul_rn(rintf(v0), pak));
                    float v1 = __fdiv_rn(p1, pak);
                    v1 = fminf(fmaxf(v1, -128.f), 127.f);
                    acc[(i2 << 1) + 1][j] = __fadd_rn(acc[(i2 << 1) + 1][j], __fmul_rn(rintf(v1), pak));
                    psum[i2][j] = 0ull;
                }
            if (q < 71) pak = __ldg(pa + ((q + 1) >> 3));
        }

        // ---- store prefetched regs into other buffer ----
        if (q < 71) {
#pragma unroll
            for (int i = 0; i < 4; i++) sA[buf ^ 1][caRow + (i << 2)][nl] = ra[i];
#pragma unroll
            for (int i = 0; i < 8; i++) sB[buf ^ 1][bRow + (i << 1)][bo] = rb[i];
            __syncthreads();
        }
    }

    // ---------------- epilogue: stores [c][n] + per-channel BN stats ----------------
    float* outT = (LAYER == 1) ? g_t1 : g_t2;
    float* ssum = (LAYER == 1) ? g_sum1 : g_sum2;
    float* ssq  = (LAYER == 1) ? g_sumsq1 : g_sumsq2;

    if (t < 128) { sRed[0][t] = 0.f; sRed[1][t] = 0.f; }
    __syncthreads();

#pragma unroll
    for (int i = 0; i < 8; i++) {
        int o = (og << 3) + i;
        float4 vv = make_float4(acc[i][0], acc[i][1], acc[i][2], acc[i][3]);
        *reinterpret_cast<float4*>(&outT[o * NPIX + n0 + (ng << 2)]) = vv;
        float s = acc[i][0] + acc[i][1] + acc[i][2] + acc[i][3];
        float qs = acc[i][0] * acc[i][0] + acc[i][1] * acc[i][1] +
                   acc[i][2] * acc[i][2] + acc[i][3] * acc[i][3];
        atomicAdd(&sRed[0][o], s);
        atomicAdd(&sRed[1][o], qs);
    }
    __syncthreads();
    if (t < 128) {
        atomicAdd(&ssum[t], sRed[0][t]);
        atomicAdd(&ssq[t],  sRed[1][t]);
    }
}

// ---------------- BN finalize ----------------
__global__ void bn_finalize_kernel(int layer, const float* __restrict__ g, const float* __restrict__ bv)
{
    int c = threadIdx.x;
    if (c < 128) {
        float sum = (layer == 1) ? g_sum1[c]   : g_sum2[c];
        float sq  = (layer == 1) ? g_sumsq1[c] : g_sumsq2[c];
        float m   = __fdiv_rn(sum, (float)NPIX);
        float var = fmaxf(__fdiv_rn(sq, (float)NPIX) - m * m, 0.f);
        float s   = __fdiv_rn(g[c], sqrtf(var + 1e-5f));
        float bb  = bv[c] - m * s;
        if (layer == 1) { g_scale1[c] = s; g_bias1[c] = bb; }
        else            { g_scale2[c] = s; g_bias2[c] = bb; }
    }
}

// ---------------- final: out = relu(bn2(t2) + identity), NCHW ----------------
__global__ void final_kernel(const float* __restrict__ x, float* __restrict__ out)
{
    int idx = blockIdx.x * blockDim.x + threadIdx.x;   // float4 index
    if (idx >= NELEM / 4) return;
    int e  = idx << 2;
    int b  = e / XSTRB;
    int r  = e - b * XSTRB;
    int c  = r / HWSZ;
    int hw = r - c * HWSZ;
    float4 xv = *reinterpret_cast<const float4*>(x + e);
    float4 tv = *reinterpret_cast<const float4*>(&g_t2[c * NPIX + b * HWSZ + hw]);
    float s = g_scale2[c], bb = g_bias2[c];
    float4 ov;
    ov.x = fmaxf(fmaf(tv.x, s, bb) + xv.x, 0.f);
    ov.y = fmaxf(fmaf(tv.y, s, bb) + xv.y, 0.f);
    ov.z = fmaxf(fmaf(tv.z, s, bb) + xv.z, 0.f);
    ov.w = fmaxf(fmaf(tv.w, s, bb) + xv.w, 0.f);
    *reinterpret_cast<float4*>(out + e) = ov;
}

// ---------------- launch ----------------
extern "C" void kernel_launch(void* const* d_in, const int* in_sizes, int n_in,
                              void* d_out, int out_size)
{
    const float* x   = (const float*)d_in[0];
    const float* w1  = (const float*)d_in[1];
    const float* wa1 = (const float*)d_in[2];
    const float* pa1 = (const float*)d_in[3];
    const float* g1  = (const float*)d_in[4];
    const float* b1  = (const float*)d_in[5];
    const float* w2  = (const float*)d_in[6];
    const float* wa2 = (const float*)d_in[7];
    const float* pa2 = (const float*)d_in[8];
    const float* g2  = (const float*)d_in[9];
    const float* b2  = (const float*)d_in[10];
    float* out = (float*)d_out;

    (void)in_sizes; (void)n_in; (void)out_size;

    prep_kernel<<<1152, 256>>>(w1, wa1, w2, wa2);
    transpose_x_kernel<<<2048, 256>>>(x);
    conv_kernel<1><<<NPIX / 64, 256>>>(pa1);
    bn_finalize_kernel<<<1, 128>>>(1, g1, b1);
    bn_apply_kernel<<<NELEM / 4 / 256, 256>>>();
    conv_kernel<2><<<NPIX / 64, 256>>>(pa2);
    bn_finalize_kernel<<<1, 128>>>(2, g2, b2);
    final_kernel<<<NELEM / 4 / 256, 256>>>(x, out);
}

// round 10
// speedup vs baseline: 1.2980x; 1.2956x over previous
#include <cuda_runtime.h>
#include <cuda_bf16.h>
#include <cstdint>

#define HH 56
#define WW 56
#define HWSZ 3136
#define XSTRB 401408
#define NELEM 6422528
#define PIMG 3364            // 58*58 padded image
#define NP 53824             // 16*3364
#define MPAD 53888           // 421*128
#define NT 421
#define ROWS_BUF (MPAD + 128) // 64 guard rows front + 128 back-pad/guard
#define NPVALID 50176.0f     // 16*56*56 real pixels
#define CHUNK_BYTES 10240    // 128 rows * 80B (32 bf16 + 8 pad)

// ---------------- device scratch ----------------
__device__ __align__(16) __nv_bfloat16 g_wb1[9*128*128];   // [k][o][c] integer weights
__device__ __align__(16) __nv_bfloat16 g_wb2[9*128*128];
__device__ __align__(16) __nv_bfloat16 g_a1[ROWS_BUF*128]; // activation split terms [n'+64][c]
__device__ __align__(16) __nv_bfloat16 g_a2[ROWS_BUF*128];
__device__ __align__(16) __nv_bfloat16 g_a3[ROWS_BUF*128];
__device__ float g_t1[MPAD*128];             // conv pre-BN outputs [n'][o]
__device__ float g_t2[MPAD*128];
__device__ float g_sum1[128], g_sq1[128], g_sum2[128], g_sq2[128];
__device__ float g_scale1[128], g_bias1[128], g_scale2[128], g_bias2[128];

// ---------------- PTX helpers ----------------
static __device__ __forceinline__ uint32_t smem_u32(const void* p) {
    uint32_t a;
    asm("{ .reg .u64 t; cvta.to.shared.u64 t, %1; cvt.u32.u64 %0, t; }" : "=r"(a) : "l"(p));
    return a;
}
static __device__ __forceinline__ void cp16(uint32_t dst, const void* src) {
    asm volatile("cp.async.cg.shared.global [%0], [%1], 16;" :: "r"(dst), "l"(src) : "memory");
}
static __device__ __forceinline__ void cp_commit() {
    asm volatile("cp.async.commit_group;" ::: "memory");
}
template <int N> static __device__ __forceinline__ void cp_wait() {
    asm volatile("cp.async.wait_group %0;" :: "n"(N) : "memory");
}
static __device__ __forceinline__ void ldsm_x4(uint32_t& r0, uint32_t& r1, uint32_t& r2,
                                               uint32_t& r3, uint32_t addr) {
    asm volatile("ldmatrix.sync.aligned.m8n8.x4.shared.b16 {%0,%1,%2,%3},[%4];"
                 : "=r"(r0), "=r"(r1), "=r"(r2), "=r"(r3) : "r"(addr));
}
static __device__ __forceinline__ void mma16816(float* c, const uint32_t* a,
                                                uint32_t b0, uint32_t b1) {
    asm volatile("mma.sync.aligned.m16n8k16.row.col.f32.bf16.bf16.f32 "
                 "{%0,%1,%2,%3},{%4,%5,%6,%7},{%8,%9},{%0,%1,%2,%3};"
                 : "+f"(c[0]), "+f"(c[1]), "+f"(c[2]), "+f"(c[3])
                 : "r"(a[0]), "r"(a[1]), "r"(a[2]), "r"(a[3]), "r"(b0), "r"(b1));
}

// ---------------- prep: integer weights (bf16) + zero stats ----------------
__global__ void prep_kernel(const float* __restrict__ w1, const float* __restrict__ wa1,
                            const float* __restrict__ w2, const float* __restrict__ wa2)
{
    if (blockIdx.x == 0 && threadIdx.x < 128) {
        int t = threadIdx.x;
        g_sum1[t] = 0.f; g_sq1[t] = 0.f; g_sum2[t] = 0.f; g_sq2[t] = 0.f;
    }
    int idx = blockIdx.x * 256 + threadIdx.x;
    if (idx < 2 * 9 * 128 * 128) {
        int layer = idx / 147456;
        int r = idx - layer * 147456;
        int k = r >> 14, o = (r >> 7) & 127, c = r & 127;
        const float* w  = layer ? w2  : w1;
        const float* wa = layer ? wa2 : wa1;
        float v = __fdiv_rn(w[(k << 14) + (o << 7) + c], wa[k]);
        v = rintf(fminf(fmaxf(v, -4.f), 3.f));
        (layer ? g_wb2 : g_wb1)[(k << 14) + (o << 7) + c] = __float2bfloat16(v);
    }
}

// ---------------- x split: NCHW -> padded [n'][c] 3-term bf16 ----------------
__global__ void xsplit_kernel(const float* __restrict__ x)
{
    __shared__ float s[128 * 57];
    int bid = blockIdx.x;
    if (bid < 928) {                       // (b, hp) padded image row
        int b = bid / 58, hp = bid % 58;
        if (hp >= 1 && hp <= 56) {
            for (int i = threadIdx.x; i < 128 * 56; i += 256) {
                int c = i / 56, w = i - c * 56;
                s[c * 57 + w] = __ldg(x + b * XSTRB + c * HWSZ + (hp - 1) * WW + w);
            }
        }
        __syncthreads();
        int np = b * PIMG + hp * 58;
        for (int i = threadIdx.x; i < 58 * 128; i += 256) {
            int px = i >> 7, c = i & 127;
            float v = 0.f;
            if (hp >= 1 && hp <= 56 && px >= 1 && px <= 56) v = s[c * 57 + (px - 1)];
            __nv_bfloat16 h1 = __float2bfloat16(v);
            float r1 = v - __bfloat162float(h1);
            __nv_bfloat16 h2 = __float2bfloat16(r1);
            float r2 = r1 - __bfloat162float(h2);
            __nv_bfloat16 h3 = __float2bfloat16(r2);
            int o = (np + px + 64) * 128 + c;
            g_a1[o] = h1; g_a2[o] = h2; g_a3[o] = h3;
        }
    } else {                               // zero guard + tile-pad rows (192 rows)
        int z0 = (bid - 928) * 24;
        for (int i = threadIdx.x; i < 24 * 128; i += 256) {
            int z = z0 + (i >> 7), c = i & 127;
            int r = (z < 64) ? z : (NP + z);   // front guards, then back region
            __nv_bfloat16 zv = __float2bfloat16(0.f);
            g_a1[r * 128 + c] = zv; g_a2[r * 128 + c] = zv; g_a3[r * 128 + c] = zv;
        }
    }
}

// ---------------- bn1 apply + relu + mask + split -> a buffers ----------------
__global__ void bnsplit_kernel()
{
    int r = blockIdx.x * 2 + (threadIdx.x >> 7);   // buffer row
    int c = threadIdx.x & 127;
    int np = r - 64;
    float v = 0.f;
    if (np >= 0 && np < NP) {
        int rp = np % PIMG;
        int hp = rp / 58, wp = rp - hp * 58;
        if (hp >= 1 && hp <= 56 && wp >= 1 && wp <= 56)
            v = fmaxf(fmaf(g_t1[np * 128 + c], g_scale1[c], g_bias1[c]), 0.f);
    }
    __nv_bfloat16 h1 = __float2bfloat16(v);
    float r1 = v - __bfloat162float(h1);
    __nv_bfloat16 h2 = __float2bfloat16(r1);
    float r2 = r1 - __bfloat162float(h2);
    __nv_bfloat16 h3 = __float2bfloat16(r2);
    int o = r * 128 + c;
    g_a1[o] = h1; g_a2[o] = h2; g_a3[o] = h3;
}

// ---------------- per-channel stats over g_t (INTERIOR PIXELS ONLY) ----------------
__global__ void stats_kernel(int layer)
{
    __shared__ float ss[128], sq[128];
    const float* src = (layer == 1) ? g_t1 : g_t2;
    int t = threadIdx.x;
    if (t < 128) { ss[t] = 0.f; sq[t] = 0.f; }
    __syncthreads();
    int c = t & 127;
    int base = blockIdx.x * 128 + (t >> 7);
    float s = 0.f, q = 0.f;
#pragma unroll 4
    for (int i = 0; i < 128; i += 2) {
        int np = base + i;
        int rp = np % PIMG;
        int hp = rp / 58, wp = rp - hp * 58;
        bool valid = (np < NP) && (hp >= 1) && (hp <= 56) && (wp >= 1) && (wp <= 56);
        float v = valid ? src[(size_t)np * 128 + c] : 0.f;
        s += v; q += v * v;
    }
    atomicAdd(&ss[c], s); atomicAdd(&sq[c], q);
    __syncthreads();
    if (t < 128) {
        atomicAdd(((layer == 1) ? g_sum1 : g_sum2) + t, ss[t]);
        atomicAdd(((layer == 1) ? g_sq1 : g_sq2) + t, sq[t]);
    }
}

// ---------------- BN finalize ----------------
__global__ void bn_finalize_kernel(int layer, const float* __restrict__ g, const float* __restrict__ bv)
{
    int c = threadIdx.x;
    if (c < 128) {
        float sum = (layer == 1) ? g_sum1[c] : g_sum2[c];
        float sq  = (layer == 1) ? g_sq1[c]  : g_sq2[c];
        float m   = __fdiv_rn(sum, NPVALID);
        float var = fmaxf(__fdiv_rn(sq, NPVALID) - m * m, 0.f);
        float s   = __fdiv_rn(g[c], sqrtf(var + 1e-5f));
        float bb  = bv[c] - m * s;
        if (layer == 1) { g_scale1[c] = s; g_bias1[c] = bb; }
        else            { g_scale2[c] = s; g_bias2[c] = bb; }
    }
}

// ---------------- chunk loader: A(128x32) + B(128x32) bf16, 80B rows ----------------
static __device__ __forceinline__ void load_chunk(int q, uint32_t dA, uint32_t dB,
                                                  int m0, const __nv_bfloat16* wb, int t)
{
    int tap = q / 12, sub = q % 12;
    int term = sub >> 2, c0 = (sub & 3) << 5;
    int tapoff = (tap % 3 - 1) * 58 + (tap / 3 - 1);
    const __nv_bfloat16* ab = (term == 0) ? g_a1 : (term == 1) ? g_a2 : g_a3;
    const __nv_bfloat16* asrc = ab + (size_t)(m0 + tapoff + 64) * 128 + c0;
    const __nv_bfloat16* bsrc = wb + (tap << 14) + c0;
#pragma unroll
    for (int p = 0; p < 2; p++) {
        int v = t + (p << 8);
        int row = v >> 2, vi = v & 3;
        cp16(dA + row * 80 + vi * 16, asrc + (size_t)row * 128 + vi * 8);
        cp16(dB + row * 80 + vi * 16, bsrc + (size_t)row * 128 + vi * 8);
    }
    cp_commit();
}

// ---------------- conv: warp-MMA 9-tap split conv with per-tap psum LSQ ----------------
template <int LAYER>
__global__ __launch_bounds__(256, 1)
void conv_kernel(const float* __restrict__ wa, const float* __restrict__ pa)
{
    __shared__ __align__(16) char smem[4 * CHUNK_BYTES];  // A0 A1 B0 B1
    uint32_t sA = smem_u32(smem);
    uint32_t sB = sA + 2 * CHUNK_BYTES;
    const int t = threadIdx.x, wid = t >> 5, lane = t & 31;
    const int wm = wid & 3, wn = wid >> 2;
    const int m0 = blockIdx.x << 7;
    const __nv_bfloat16* wb = (LAYER == 1) ? g_wb1 : g_wb2;

    float psum[2][8][4];
    float acc [2][8][4];
#pragma unroll
    for (int mi = 0; mi < 2; mi++)
#pragma unroll
        for (int nq = 0; nq < 8; nq++)
#pragma unroll
            for (int e = 0; e < 4; e++) { psum[mi][nq][e] = 0.f; acc[mi][nq][e] = 0.f; }

    // ldmatrix base addresses (per lane)
    const uint32_t aAddr = sA + (wm * 32 + (lane & 15)) * 80 + ((lane >> 4) << 4);
    const uint32_t bAddr = sB + (wn * 64 + (lane & 7) + ((lane >> 4) << 3)) * 80
                              + (((lane >> 3) & 1) << 4);

    load_chunk(0, sA, sB, m0, wb, t);

#pragma unroll 1
    for (int q = 0; q < 108; q++) {
        const uint32_t bufo = (q & 1) * CHUNK_BYTES;
        if (q < 107) {
            load_chunk(q + 1, sA + ((q + 1) & 1) * CHUNK_BYTES,
                       sB + ((q + 1) & 1) * CHUNK_BYTES, m0, wb, t);
            cp_wait<1>();
        } else {
            cp_wait<0>();
        }
        __syncthreads();

#pragma unroll
        for (int kt = 0; kt < 2; kt++) {
            uint32_t a[2][4], b[4][4];
#pragma unroll
            for (int mi = 0; mi < 2; mi++)
                ldsm_x4(a[mi][0], a[mi][1], a[mi][2], a[mi][3],
                        aAddr + bufo + mi * 16 * 80 + kt * 32);
#pragma unroll
            for (int nj = 0; nj < 4; nj++)
                ldsm_x4(b[nj][0], b[nj][1], b[nj][2], b[nj][3],
                        bAddr + bufo + nj * 16 * 80 + kt * 32);
#pragma unroll
            for (int mi = 0; mi < 2; mi++)
#pragma unroll
                for (int nq = 0; nq < 8; nq++)
                    mma16816(psum[mi][nq], a[mi], b[nq >> 1][(nq & 1) * 2],
                             b[nq >> 1][(nq & 1) * 2 + 1]);
        }

        if (q % 12 == 11) {                 // tap boundary: LSQ quantize psum -> acc
            int tap = q / 12;
            float ak = __ldg(wa + tap), pk = __ldg(pa + tap);
#pragma unroll
            for (int mi = 0; mi < 2; mi++)
#pragma unroll
                for (int nq = 0; nq < 8; nq++)
#pragma unroll
                    for (int e = 0; e < 4; e++) {
                        float v = __fdiv_rn(__fmul_rn(psum[mi][nq][e], ak), pk);
                        v = fminf(fmaxf(v, -128.f), 127.f);
                        acc[mi][nq][e] = __fadd_rn(acc[mi][nq][e], __fmul_rn(rintf(v), pk));
                        psum[mi][nq][e] = 0.f;
                    }
        }
        __syncthreads();
    }

    // ---- store pre-BN outputs [n'][o] ----
    float* tout = (LAYER == 1) ? g_t1 : g_t2;
#pragma unroll
    for (int mi = 0; mi < 2; mi++) {
        int row0 = m0 + wm * 32 + mi * 16 + (lane >> 2);
#pragma unroll
        for (int nq = 0; nq < 8; nq++) {
            int col = wn * 64 + nq * 8 + (lane & 3) * 2;
            *reinterpret_cast<float2*>(tout + (size_t)row0 * 128 + col) =
                make_float2(acc[mi][nq][0], acc[mi][nq][1]);
            *reinterpret_cast<float2*>(tout + (size_t)(row0 + 8) * 128 + col) =
                make_float2(acc[mi][nq][2], acc[mi][nq][3]);
        }
    }
}

// ---------------- final: out = relu(bn2(t2) + x), NCHW ----------------
__global__ void final_kernel(const float* __restrict__ x, float* __restrict__ out)
{
    __shared__ float s[56 * 129];
    int b = blockIdx.x / 56, h = blockIdx.x % 56;
    int np0 = b * PIMG + (h + 1) * 58 + 1;
    for (int i = threadIdx.x; i < 56 * 128; i += 256) {
        int w = i >> 7, c = i & 127;
        s[w * 129 + c] = g_t2[(size_t)(np0 + w) * 128 + c];
    }
    __syncthreads();
    for (int i = threadIdx.x; i < 56 * 128; i += 256) {
        int c = i / 56, w = i - c * 56;
        int e = b * XSTRB + c * HWSZ + h * 56 + w;
        out[e] = fmaxf(fmaf(s[w * 129 + c], g_scale2[c], g_bias2[c]) + __ldg(x + e), 0.f);
    }
}

// ---------------- launch ----------------
extern "C" void kernel_launch(void* const* d_in, const int* in_sizes, int n_in,
                              void* d_out, int out_size)
{
    const float* x   = (const float*)d_in[0];
    const float* w1  = (const float*)d_in[1];
    const float* wa1 = (const float*)d_in[2];
    const float* pa1 = (const float*)d_in[3];
    const float* g1  = (const float*)d_in[4];
    const float* b1  = (const float*)d_in[5];
    const float* w2  = (const float*)d_in[6];
    const float* wa2 = (const float*)d_in[7];
    const float* pa2 = (const float*)d_in[8];
    const float* g2  = (const float*)d_in[9];
    const float* b2  = (const float*)d_in[10];
    float* out = (float*)d_out;
    (void)in_sizes; (void)n_in; (void)out_size;

    prep_kernel<<<1152, 256>>>(w1, wa1, w2, wa2);
    xsplit_kernel<<<936, 256>>>(x);
    conv_kernel<1><<<NT, 256>>>(wa1, pa1);
    stats_kernel<<<NT, 256>>>(1);
    bn_finalize_kernel<<<1, 128>>>(1, g1, b1);
    bnsplit_kernel<<<ROWS_BUF / 2, 256>>>();
    conv_kernel<2><<<NT, 256>>>(wa2, pa2);
    stats_kernel<<<NT, 256>>>(2);
    bn_finalize_kernel<<<1, 128>>>(2, g2, b2);
    final_kernel<<<896, 256>>>(x, out);
}

// round 11
// speedup vs baseline: 1.8798x; 1.4483x over previous
#include <cuda_runtime.h>
#include <cuda_bf16.h>
#include <cstdint>

#define HH 56
#define WW 56
#define HWSZ 3136
#define XSTRB 401408
#define NELEM 6422528
#define PIMG 3364            // 58*58 padded image
#define NP 53824             // 16*3364
#define MPAD 53888           // 421*128
#define NT 421
#define ROWS_BUF (MPAD + 128) // 64 guard rows front + 128 back-pad/guard
#define NPVALID 50176.0f     // 16*56*56 real pixels
#define ROWB 144             // 64 bf16 (128B) + 16B pad
#define TILE_B (128 * ROWB)  // 18432
#define STAGE_B (2 * TILE_B) // 36864: A then B
#define NSTAGE 4
#define SMEM_CONV (NSTAGE * STAGE_B)   // 147456
#define NCHUNK 54            // 9 taps * 3 terms * 2 k64-halves

// ---------------- device scratch ----------------
__device__ __align__(16) __nv_bfloat16 g_wb1[9*128*128];   // [k][o][c] integer weights
__device__ __align__(16) __nv_bfloat16 g_wb2[9*128*128];
__device__ __align__(16) __nv_bfloat16 g_a1[ROWS_BUF*128]; // activation split terms [n'+64][c]
__device__ __align__(16) __nv_bfloat16 g_a2[ROWS_BUF*128];
__device__ __align__(16) __nv_bfloat16 g_a3[ROWS_BUF*128];
__device__ float g_t1[MPAD*128];             // conv pre-BN outputs [n'][o]
__device__ float g_t2[MPAD*128];
__device__ float g_sum1[128], g_sq1[128], g_sum2[128], g_sq2[128];
__device__ float g_scale1[128], g_bias1[128], g_scale2[128], g_bias2[128];

// ---------------- PTX helpers ----------------
static __device__ __forceinline__ uint32_t smem_u32(const void* p) {
    uint32_t a;
    asm("{ .reg .u64 t; cvta.to.shared.u64 t, %1; cvt.u32.u64 %0, t; }" : "=r"(a) : "l"(p));
    return a;
}
static __device__ __forceinline__ void cp16(uint32_t dst, const void* src) {
    asm volatile("cp.async.cg.shared.global [%0], [%1], 16;" :: "r"(dst), "l"(src) : "memory");
}
static __device__ __forceinline__ void cp_commit() {
    asm volatile("cp.async.commit_group;" ::: "memory");
}
template <int N> static __device__ __forceinline__ void cp_wait() {
    asm volatile("cp.async.wait_group %0;" :: "n"(N) : "memory");
}
static __device__ __forceinline__ void ldsm_x4(uint32_t& r0, uint32_t& r1, uint32_t& r2,
                                               uint32_t& r3, uint32_t addr) {
    asm volatile("ldmatrix.sync.aligned.m8n8.x4.shared.b16 {%0,%1,%2,%3},[%4];"
                 : "=r"(r0), "=r"(r1), "=r"(r2), "=r"(r3) : "r"(addr));
}
static __device__ __forceinline__ void mma16816(float* c, const uint32_t* a,
                                                uint32_t b0, uint32_t b1) {
    asm volatile("mma.sync.aligned.m16n8k16.row.col.f32.bf16.bf16.f32 "
                 "{%0,%1,%2,%3},{%4,%5,%6,%7},{%8,%9},{%0,%1,%2,%3};"
                 : "+f"(c[0]), "+f"(c[1]), "+f"(c[2]), "+f"(c[3])
                 : "r"(a[0]), "r"(a[1]), "r"(a[2]), "r"(a[3]), "r"(b0), "r"(b1));
}

// ---------------- prep: integer weights (bf16) + zero stats ----------------
__global__ void prep_kernel(const float* __restrict__ w1, const float* __restrict__ wa1,
                            const float* __restrict__ w2, const float* __restrict__ wa2)
{
    if (blockIdx.x == 0 && threadIdx.x < 128) {
        int t = threadIdx.x;
        g_sum1[t] = 0.f; g_sq1[t] = 0.f; g_sum2[t] = 0.f; g_sq2[t] = 0.f;
    }
    int idx = blockIdx.x * 256 + threadIdx.x;
    if (idx < 2 * 9 * 128 * 128) {
        int layer = idx / 147456;
        int r = idx - layer * 147456;
        int k = r >> 14, o = (r >> 7) & 127, c = r & 127;
        const float* w  = layer ? w2  : w1;
        const float* wa = layer ? wa2 : wa1;
        float v = __fdiv_rn(w[(k << 14) + (o << 7) + c], wa[k]);
        v = rintf(fminf(fmaxf(v, -4.f), 3.f));
        (layer ? g_wb2 : g_wb1)[(k << 14) + (o << 7) + c] = __float2bfloat16(v);
    }
}

// ---------------- x split: NCHW -> padded [n'][c] 3-term bf16 ----------------
__global__ void xsplit_kernel(const float* __restrict__ x)
{
    __shared__ float s[128 * 57];
    int bid = blockIdx.x;
    if (bid < 928) {                       // (b, hp) padded image row
        int b = bid / 58, hp = bid % 58;
        if (hp >= 1 && hp <= 56) {
            for (int i = threadIdx.x; i < 128 * 56; i += 256) {
                int c = i / 56, w = i - c * 56;
                s[c * 57 + w] = __ldg(x + b * XSTRB + c * HWSZ + (hp - 1) * WW + w);
            }
        }
        __syncthreads();
        int np = b * PIMG + hp * 58;
        for (int i = threadIdx.x; i < 58 * 128; i += 256) {
            int px = i >> 7, c = i & 127;
            float v = 0.f;
            if (hp >= 1 && hp <= 56 && px >= 1 && px <= 56) v = s[c * 57 + (px - 1)];
            __nv_bfloat16 h1 = __float2bfloat16(v);
            float r1 = v - __bfloat162float(h1);
            __nv_bfloat16 h2 = __float2bfloat16(r1);
            float r2 = r1 - __bfloat162float(h2);
            __nv_bfloat16 h3 = __float2bfloat16(r2);
            int o = (np + px + 64) * 128 + c;
            g_a1[o] = h1; g_a2[o] = h2; g_a3[o] = h3;
        }
    } else {                               // zero guard + tile-pad rows (192 rows)
        int z0 = (bid - 928) * 24;
        for (int i = threadIdx.x; i < 24 * 128; i += 256) {
            int z = z0 + (i >> 7), c = i & 127;
            int r = (z < 64) ? z : (NP + z);   // front guards, then back region
            __nv_bfloat16 zv = __float2bfloat16(0.f);
            g_a1[r * 128 + c] = zv; g_a2[r * 128 + c] = zv; g_a3[r * 128 + c] = zv;
        }
    }
}

// ---------------- bn1 apply + relu + mask + split -> a buffers ----------------
__global__ void bnsplit_kernel()
{
    int r = blockIdx.x * 2 + (threadIdx.x >> 7);   // buffer row
    int c = threadIdx.x & 127;
    int np = r - 64;
    float v = 0.f;
    if (np >= 0 && np < NP) {
        int rp = np % PIMG;
        int hp = rp / 58, wp = rp - hp * 58;
        if (hp >= 1 && hp <= 56 && wp >= 1 && wp <= 56)
            v = fmaxf(fmaf(g_t1[np * 128 + c], g_scale1[c], g_bias1[c]), 0.f);
    }
    __nv_bfloat16 h1 = __float2bfloat16(v);
    float r1 = v - __bfloat162float(h1);
    __nv_bfloat16 h2 = __float2bfloat16(r1);
    float r2 = r1 - __bfloat162float(h2);
    __nv_bfloat16 h3 = __float2bfloat16(r2);
    int o = r * 128 + c;
    g_a1[o] = h1; g_a2[o] = h2; g_a3[o] = h3;
}

// ---------------- BN finalize ----------------
__global__ void bn_finalize_kernel(int layer, const float* __restrict__ g, const float* __restrict__ bv)
{
    int c = threadIdx.x;
    if (c < 128) {
        float sum = (layer == 1) ? g_sum1[c] : g_sum2[c];
        float sq  = (layer == 1) ? g_sq1[c]  : g_sq2[c];
        float m   = __fdiv_rn(sum, NPVALID);
        float var = fmaxf(__fdiv_rn(sq, NPVALID) - m * m, 0.f);
        float s   = __fdiv_rn(g[c], sqrtf(var + 1e-5f));
        float bb  = bv[c] - m * s;
        if (layer == 1) { g_scale1[c] = s; g_bias1[c] = bb; }
        else            { g_scale2[c] = s; g_bias2[c] = bb; }
    }
}

// ---------------- chunk loader: A(128x64) + B(128x64) bf16, 144B rows ----------------
static __device__ __forceinline__ void load_chunk(int q, uint32_t dA, uint32_t dB,
                                                  int m0, const __nv_bfloat16* wb, int t)
{
    int tap = q / 6, sub = q % 6;
    int term = sub >> 1, c0 = (sub & 1) << 6;
    int tapoff = (tap % 3 - 1) * 58 + (tap / 3 - 1);
    const __nv_bfloat16* ab = (term == 0) ? g_a1 : (term == 1) ? g_a2 : g_a3;
    const __nv_bfloat16* asrc = ab + (size_t)(m0 + tapoff + 64) * 128 + c0;
    const __nv_bfloat16* bsrc = wb + (tap << 14) + c0;
#pragma unroll
    for (int p = 0; p < 2; p++) {
        int v = t + (p << 9);              // 0..1023
        int row = v >> 3, col = v & 7;
        cp16(dA + row * ROWB + col * 16, asrc + (size_t)row * 128 + col * 8);
        cp16(dB + row * ROWB + col * 16, bsrc + (size_t)row * 128 + col * 8);
    }
    cp_commit();
}

// ---------------- conv: warp-MMA 9-tap split conv, fused BN stats ----------------
template <int LAYER>
__global__ __launch_bounds__(512, 1)
void conv_kernel(const float* __restrict__ wa, const float* __restrict__ pa)
{
    extern __shared__ __align__(16) char dsm[];
    __shared__ float sRed[2][128];
    uint32_t sm0 = smem_u32(dsm);
    const int t = threadIdx.x, wid = t >> 5, lane = t & 31;
    const int wm = wid & 3, wn = wid >> 2;          // 4x4 warp grid, 32x32 tiles
    const int m0 = blockIdx.x << 7;
    const __nv_bfloat16* wb = (LAYER == 1) ? g_wb1 : g_wb2;

    float psum[2][4][4];
    float acc [2][4][4];
#pragma unroll
    for (int mi = 0; mi < 2; mi++)
#pragma unroll
        for (int nq = 0; nq < 4; nq++)
#pragma unroll
            for (int e = 0; e < 4; e++) { psum[mi][nq][e] = 0.f; acc[mi][nq][e] = 0.f; }

    // ldmatrix lane bases (within a stage's A/B tile)
    const uint32_t aOff = (uint32_t)(wm * 32 + (lane & 15)) * ROWB + ((lane >> 4) << 4);
    const uint32_t bOff = (uint32_t)(wn * 32 + (lane & 7) + ((lane >> 4) << 3)) * ROWB
                          + (((lane >> 3) & 1) << 4);

    load_chunk(0, sm0, sm0 + TILE_B, m0, wb, t);
    load_chunk(1, sm0 + STAGE_B, sm0 + STAGE_B + TILE_B, m0, wb, t);
    load_chunk(2, sm0 + 2 * STAGE_B, sm0 + 2 * STAGE_B + TILE_B, m0, wb, t);

#pragma unroll 1
    for (int q = 0; q < NCHUNK; q++) {
        if (q < NCHUNK - 2)      cp_wait<2>();
        else if (q == NCHUNK - 2) cp_wait<1>();
        else                      cp_wait<0>();
        __syncthreads();
        if (q + 3 < NCHUNK) {
            uint32_t sb = sm0 + ((q + 3) & 3) * STAGE_B;
            load_chunk(q + 3, sb, sb + TILE_B, m0, wb, t);
        }
        const uint32_t stg = sm0 + (q & 3) * STAGE_B;
        const uint32_t aA = stg + aOff;
        const uint32_t bA = stg + TILE_B + bOff;

#pragma unroll
        for (int kt = 0; kt < 4; kt++) {
            uint32_t a[2][4], b[2][4];
#pragma unroll
            for (int mi = 0; mi < 2; mi++)
                ldsm_x4(a[mi][0], a[mi][1], a[mi][2], a[mi][3],
                        aA + mi * 16 * ROWB + kt * 32);
#pragma unroll
            for (int nj = 0; nj < 2; nj++)
                ldsm_x4(b[nj][0], b[nj][1], b[nj][2], b[nj][3],
                        bA + nj * 16 * ROWB + kt * 32);
#pragma unroll
            for (int mi = 0; mi < 2; mi++)
#pragma unroll
                for (int nq = 0; nq < 4; nq++)
                    mma16816(psum[mi][nq], a[mi], b[nq >> 1][(nq & 1) * 2],
                             b[nq >> 1][(nq & 1) * 2 + 1]);
        }

        if (q % 6 == 5) {                   // tap boundary: LSQ quantize psum -> acc
            int tap = q / 6;
            float ak = __ldg(wa + tap), pk = __ldg(pa + tap);
#pragma unroll
            for (int mi = 0; mi < 2; mi++)
#pragma unroll
                for (int nq = 0; nq < 4; nq++)
#pragma unroll
                    for (int e = 0; e < 4; e++) {
                        float v = __fdiv_rn(__fmul_rn(psum[mi][nq][e], ak), pk);
                        v = fminf(fmaxf(v, -128.f), 127.f);
                        acc[mi][nq][e] = __fadd_rn(acc[mi][nq][e], __fmul_rn(rintf(v), pk));
                        psum[mi][nq][e] = 0.f;
                    }
        }
    }

    // ---- store pre-BN outputs [n'][o] ----
    float* tout = (LAYER == 1) ? g_t1 : g_t2;
#pragma unroll
    for (int mi = 0; mi < 2; mi++) {
        int row0 = m0 + wm * 32 + mi * 16 + (lane >> 2);
#pragma unroll
        for (int nq = 0; nq < 4; nq++) {
            int col = wn * 32 + nq * 8 + (lane & 3) * 2;
            *reinterpret_cast<float2*>(tout + (size_t)row0 * 128 + col) =
                make_float2(acc[mi][nq][0], acc[mi][nq][1]);
            *reinterpret_cast<float2*>(tout + (size_t)(row0 + 8) * 128 + col) =
                make_float2(acc[mi][nq][2], acc[mi][nq][3]);
        }
    }

    // ---- fused BN stats (interior pixels only) ----
    if (t < 128) { sRed[0][t] = 0.f; sRed[1][t] = 0.f; }
    __syncthreads();
#pragma unroll
    for (int mi = 0; mi < 2; mi++) {
#pragma unroll
        for (int rr = 0; rr < 2; rr++) {
            int np = m0 + wm * 32 + mi * 16 + (lane >> 2) + rr * 8;
            int rp = np % PIMG;
            int hp = rp / 58, wp = rp - hp * 58;
            float msk = ((np < NP) && hp >= 1 && hp <= 56 && wp >= 1 && wp <= 56) ? 1.f : 0.f;
#pragma unroll
            for (int nq = 0; nq < 4; nq++)
#pragma unroll
                for (int e2 = 0; e2 < 2; e2++) {
                    float v = acc[mi][nq][rr * 2 + e2] * msk;
                    float sv = v, qv = v * v;
#pragma unroll
                    for (int d = 4; d <= 16; d <<= 1) {
                        sv += __shfl_xor_sync(0xffffffffu, sv, d);
                        qv += __shfl_xor_sync(0xffffffffu, qv, d);
                    }
                    if (lane < 4) {
                        int col = wn * 32 + nq * 8 + lane * 2 + e2;
                        atomicAdd(&sRed[0][col], sv);
                        atomicAdd(&sRed[1][col], qv);
                    }
                }
        }
    }
    __syncthreads();
    if (t < 128) {
        atomicAdd(((LAYER == 1) ? g_sum1 : g_sum2) + t, sRed[0][t]);
        atomicAdd(((LAYER == 1) ? g_sq1 : g_sq2) + t, sRed[1][t]);
    }
}

// ---------------- final: out = relu(bn2(t2) + x), NCHW ----------------
__global__ void final_kernel(const float* __restrict__ x, float* __restrict__ out)
{
    __shared__ float s[56 * 129];
    int b = blockIdx.x / 56, h = blockIdx.x % 56;
    int np0 = b * PIMG + (h + 1) * 58 + 1;
    for (int i = threadIdx.x; i < 56 * 128; i += 256) {
        int w = i >> 7, c = i & 127;
        s[w * 129 + c] = g_t2[(size_t)(np0 + w) * 128 + c];
    }
    __syncthreads();
    for (int i = threadIdx.x; i < 56 * 128; i += 256) {
        int c = i / 56, w = i - c * 56;
        int e = b * XSTRB + c * HWSZ + h * 56 + w;
        out[e] = fmaxf(fmaf(s[w * 129 + c], g_scale2[c], g_bias2[c]) + __ldg(x + e), 0.f);
    }
}

// ---------------- launch ----------------
extern "C" void kernel_launch(void* const* d_in, const int* in_sizes, int n_in,
                              void* d_out, int out_size)
{
    const float* x   = (const float*)d_in[0];
    const float* w1  = (const float*)d_in[1];
    const float* wa1 = (const float*)d_in[2];
    const float* pa1 = (const float*)d_in[3];
    const float* g1  = (const float*)d_in[4];
    const float* b1  = (const float*)d_in[5];
    const float* w2  = (const float*)d_in[6];
    const float* wa2 = (const float*)d_in[7];
    const float* pa2 = (const float*)d_in[8];
    const float* g2  = (const float*)d_in[9];
    const float* b2  = (const float*)d_in[10];
    float* out = (float*)d_out;
    (void)in_sizes; (void)n_in; (void)out_size;

    cudaFuncSetAttribute(conv_kernel<1>, cudaFuncAttributeMaxDynamicSharedMemorySize, SMEM_CONV);
    cudaFuncSetAttribute(conv_kernel<2>, cudaFuncAttributeMaxDynamicSharedMemorySize, SMEM_CONV);

    prep_kernel<<<1152, 256>>>(w1, wa1, w2, wa2);
    xsplit_kernel<<<936, 256>>>(x);
    conv_kernel<1><<<NT, 512, SMEM_CONV>>>(wa1, pa1);
    bn_finalize_kernel<<<1, 128>>>(1, g1, b1);
    bnsplit_kernel<<<ROWS_BUF / 2, 256>>>();
    conv_kernel<2><<<NT, 512, SMEM_CONV>>>(wa2, pa2);
    bn_finalize_kernel<<<1, 128>>>(2, g2, b2);
    final_kernel<<<896, 256>>>(x, out);
}

// round 12
// speedup vs baseline: 2.2057x; 1.1734x over previous
#include <cuda_runtime.h>
#include <cuda_bf16.h>
#include <cstdint>

#define HH 56
#define WW 56
#define HWSZ 3136
#define XSTRB 401408
#define NELEM 6422528
#define PIMG 3364            // 58*58 padded image
#define NP 53824             // 16*3364
#define MPAD 53888           // 421*128
#define NT 421
#define ROWS_BUF (MPAD + 128) // 64 guard rows front + 128 back-pad/guard
#define NPVALID 50176.0f     // 16*56*56 real pixels
#define ROWB 144             // 64 bf16 (128B) + 16B pad
#define TILE_B (128 * ROWB)  // 18432
#define STAGE_B (4 * TILE_B) // 73728: B, A1, A2, A3
#define SMEM_CONV (2 * STAGE_B)   // 147456
#define NITER 18             // 9 taps * 2 k64-halves

// ---------------- device scratch ----------------
__device__ __align__(16) __nv_bfloat16 g_wb1[9*128*128];   // [k][o][c] integer weights
__device__ __align__(16) __nv_bfloat16 g_wb2[9*128*128];
__device__ __align__(16) __nv_bfloat16 g_a1[ROWS_BUF*128]; // activation split terms [n'+64][c]
__device__ __align__(16) __nv_bfloat16 g_a2[ROWS_BUF*128];
__device__ __align__(16) __nv_bfloat16 g_a3[ROWS_BUF*128];
__device__ float g_t1[MPAD*128];             // conv pre-BN outputs [n'][o]
__device__ float g_t2[MPAD*128];
__device__ float g_sum1[128], g_sq1[128], g_sum2[128], g_sq2[128];
__device__ float g_scale1[128], g_bias1[128], g_scale2[128], g_bias2[128];

// ---------------- PTX helpers ----------------
static __device__ __forceinline__ uint32_t smem_u32(const void* p) {
    uint32_t a;
    asm("{ .reg .u64 t; cvta.to.shared.u64 t, %1; cvt.u32.u64 %0, t; }" : "=r"(a) : "l"(p));
    return a;
}
static __device__ __forceinline__ void cp16(uint32_t dst, const void* src) {
    asm volatile("cp.async.cg.shared.global [%0], [%1], 16;" :: "r"(dst), "l"(src) : "memory");
}
static __device__ __forceinline__ void cp_commit() {
    asm volatile("cp.async.commit_group;" ::: "memory");
}
template <int N> static __device__ __forceinline__ void cp_wait() {
    asm volatile("cp.async.wait_group %0;" :: "n"(N) : "memory");
}
static __device__ __forceinline__ void ldsm_x4(uint32_t& r0, uint32_t& r1, uint32_t& r2,
                                               uint32_t& r3, uint32_t addr) {
    asm volatile("ldmatrix.sync.aligned.m8n8.x4.shared.b16 {%0,%1,%2,%3},[%4];"
                 : "=r"(r0), "=r"(r1), "=r"(r2), "=r"(r3) : "r"(addr));
}
static __device__ __forceinline__ void mma16816(float* c, const uint32_t* a,
                                                uint32_t b0, uint32_t b1) {
    asm volatile("mma.sync.aligned.m16n8k16.row.col.f32.bf16.bf16.f32 "
                 "{%0,%1,%2,%3},{%4,%5,%6,%7},{%8,%9},{%0,%1,%2,%3};"
                 : "+f"(c[0]), "+f"(c[1]), "+f"(c[2]), "+f"(c[3])
                 : "r"(a[0]), "r"(a[1]), "r"(a[2]), "r"(a[3]), "r"(b0), "r"(b1));
}

// ---------------- prep: integer weights (bf16) + zero stats ----------------
__global__ void prep_kernel(const float* __restrict__ w1, const float* __restrict__ wa1,
                            const float* __restrict__ w2, const float* __restrict__ wa2)
{
    if (blockIdx.x == 0 && threadIdx.x < 128) {
        int t = threadIdx.x;
        g_sum1[t] = 0.f; g_sq1[t] = 0.f; g_sum2[t] = 0.f; g_sq2[t] = 0.f;
    }
    int idx = blockIdx.x * 256 + threadIdx.x;
    if (idx < 2 * 9 * 128 * 128) {
        int layer = idx / 147456;
        int r = idx - layer * 147456;
        int k = r >> 14, o = (r >> 7) & 127, c = r & 127;
        const float* w  = layer ? w2  : w1;
        const float* wa = layer ? wa2 : wa1;
        float v = __fdiv_rn(w[(k << 14) + (o << 7) + c], wa[k]);
        v = rintf(fminf(fmaxf(v, -4.f), 3.f));
        (layer ? g_wb2 : g_wb1)[(k << 14) + (o << 7) + c] = __float2bfloat16(v);
    }
}

// ---------------- x split: NCHW -> padded [n'][c] 3-term bf16 ----------------
__global__ void xsplit_kernel(const float* __restrict__ x)
{
    __shared__ float s[128 * 57];
    int bid = blockIdx.x;
    if (bid < 928) {                       // (b, hp) padded image row
        int b = bid / 58, hp = bid % 58;
        if (hp >= 1 && hp <= 56) {
            for (int i = threadIdx.x; i < 128 * 56; i += 256) {
                int c = i / 56, w = i - c * 56;
                s[c * 57 + w] = __ldg(x + b * XSTRB + c * HWSZ + (hp - 1) * WW + w);
            }
        }
        __syncthreads();
        int np = b * PIMG + hp * 58;
        for (int i = threadIdx.x; i < 58 * 128; i += 256) {
            int px = i >> 7, c = i & 127;
            float v = 0.f;
            if (hp >= 1 && hp <= 56 && px >= 1 && px <= 56) v = s[c * 57 + (px - 1)];
            __nv_bfloat16 h1 = __float2bfloat16(v);
            float r1 = v - __bfloat162float(h1);
            __nv_bfloat16 h2 = __float2bfloat16(r1);
            float r2 = r1 - __bfloat162float(h2);
            __nv_bfloat16 h3 = __float2bfloat16(r2);
            int o = (np + px + 64) * 128 + c;
            g_a1[o] = h1; g_a2[o] = h2; g_a3[o] = h3;
        }
    } else {                               // zero guard + tile-pad rows (192 rows)
        int z0 = (bid - 928) * 24;
        for (int i = threadIdx.x; i < 24 * 128; i += 256) {
            int z = z0 + (i >> 7), c = i & 127;
            int r = (z < 64) ? z : (NP + z);   // front guards, then back region
            __nv_bfloat16 zv = __float2bfloat16(0.f);
            g_a1[r * 128 + c] = zv; g_a2[r * 128 + c] = zv; g_a3[r * 128 + c] = zv;
        }
    }
}

// ---------------- bn1 apply + relu + mask + split -> a buffers ----------------
__global__ void bnsplit_kernel()
{
    int r = blockIdx.x * 2 + (threadIdx.x >> 7);   // buffer row
    int c = threadIdx.x & 127;
    int np = r - 64;
    float v = 0.f;
    if (np >= 0 && np < NP) {
        int rp = np % PIMG;
        int hp = rp / 58, wp = rp - hp * 58;
        if (hp >= 1 && hp <= 56 && wp >= 1 && wp <= 56)
            v = fmaxf(fmaf(g_t1[np * 128 + c], g_scale1[c], g_bias1[c]), 0.f);
    }
    __nv_bfloat16 h1 = __float2bfloat16(v);
    float r1 = v - __bfloat162float(h1);
    __nv_bfloat16 h2 = __float2bfloat16(r1);
    float r2 = r1 - __bfloat162float(h2);
    __nv_bfloat16 h3 = __float2bfloat16(r2);
    int o = r * 128 + c;
    g_a1[o] = h1; g_a2[o] = h2; g_a3[o] = h3;
}

// ---------------- BN finalize ----------------
__global__ void bn_finalize_kernel(int layer, const float* __restrict__ g, const float* __restrict__ bv)
{
    int c = threadIdx.x;
    if (c < 128) {
        float sum = (layer == 1) ? g_sum1[c] : g_sum2[c];
        float sq  = (layer == 1) ? g_sq1[c]  : g_sq2[c];
        float m   = __fdiv_rn(sum, NPVALID);
        float var = fmaxf(__fdiv_rn(sq, NPVALID) - m * m, 0.f);
        float s   = __fdiv_rn(g[c], sqrtf(var + 1e-5f));
        float bb  = bv[c] - m * s;
        if (layer == 1) { g_scale1[c] = s; g_bias1[c] = bb; }
        else            { g_scale2[c] = s; g_bias2[c] = bb; }
    }
}

// ---------------- stage loader: B + 3 A-term tiles (each 128x64 bf16) ----------------
static __device__ __forceinline__ void load_stage(int it, uint32_t sbase, int m0,
                                                  const __nv_bfloat16* wb, int t)
{
    const int tap = it >> 1, half = it & 1;
    const int c0 = half << 6;
    const int tapoff = (tap % 3 - 1) * 58 + (tap / 3 - 1);
    const __nv_bfloat16* srcs[4];
    srcs[0] = wb + (tap << 14) + c0;
    srcs[1] = g_a1 + (size_t)(m0 + tapoff + 64) * 128 + c0;
    srcs[2] = g_a2 + (size_t)(m0 + tapoff + 64) * 128 + c0;
    srcs[3] = g_a3 + (size_t)(m0 + tapoff + 64) * 128 + c0;
#pragma unroll
    for (int tile = 0; tile < 4; tile++) {
        const __nv_bfloat16* src = srcs[tile];
        uint32_t dst = sbase + tile * TILE_B;
#pragma unroll
        for (int p = 0; p < 2; p++) {
            int v = t + (p << 9);          // 0..1023
            int row = v >> 3, col = v & 7;
            cp16(dst + row * ROWB + col * 16, src + (size_t)row * 128 + col * 8);
        }
    }
    cp_commit();
}

// ---------------- conv: warp-MMA 9-tap split conv, fused BN stats ----------------
template <int LAYER>
__global__ __launch_bounds__(512, 1)
void conv_kernel(const float* __restrict__ wa, const float* __restrict__ pa)
{
    extern __shared__ __align__(16) char dsm[];
    __shared__ float sRed[2][128];
    uint32_t sm0 = smem_u32(dsm);
    const int t = threadIdx.x, wid = t >> 5, lane = t & 31;
    const int wm = wid & 3, wn = wid >> 2;          // 4x4 warp grid, 32x32 tiles
    const int m0 = blockIdx.x << 7;
    const __nv_bfloat16* wb = (LAYER == 1) ? g_wb1 : g_wb2;

    float psum[2][4][4];
    float acc [2][4][4];
#pragma unroll
    for (int mi = 0; mi < 2; mi++)
#pragma unroll
        for (int nq = 0; nq < 4; nq++)
#pragma unroll
            for (int e = 0; e < 4; e++) { psum[mi][nq][e] = 0.f; acc[mi][nq][e] = 0.f; }

    // ldmatrix lane bases (within a tile)
    const uint32_t aOff = (uint32_t)(wm * 32 + (lane & 15)) * ROWB + ((lane >> 4) << 4);
    const uint32_t bOff = (uint32_t)(wn * 32 + (lane & 7) + ((lane >> 4) << 3)) * ROWB
                          + (((lane >> 3) & 1) << 4);

    load_stage(0, sm0, m0, wb, t);

#pragma unroll 1
    for (int it = 0; it < NITER; it++) {
        cp_wait<0>();
        __syncthreads();
        if (it + 1 < NITER)
            load_stage(it + 1, sm0 + ((it + 1) & 1) * STAGE_B, m0, wb, t);

        const uint32_t stg = sm0 + (it & 1) * STAGE_B;
        const uint32_t bA = stg + bOff;

#pragma unroll
        for (int kt = 0; kt < 4; kt++) {
            uint32_t b[2][4];
#pragma unroll
            for (int nj = 0; nj < 2; nj++)
                ldsm_x4(b[nj][0], b[nj][1], b[nj][2], b[nj][3],
                        bA + nj * 16 * ROWB + kt * 32);
#pragma unroll
            for (int term = 0; term < 3; term++) {
                const uint32_t aA = stg + (1 + term) * TILE_B + aOff;
                uint32_t a[2][4];
#pragma unroll
                for (int mi = 0; mi < 2; mi++)
                    ldsm_x4(a[mi][0], a[mi][1], a[mi][2], a[mi][3],
                            aA + mi * 16 * ROWB + kt * 32);
#pragma unroll
                for (int mi = 0; mi < 2; mi++)
#pragma unroll
                    for (int nq = 0; nq < 4; nq++)
                        mma16816(psum[mi][nq], a[mi], b[nq >> 1][(nq & 1) * 2],
                                 b[nq >> 1][(nq & 1) * 2 + 1]);
            }
        }

        if (it & 1) {                       // tap boundary: LSQ quantize psum -> acc
            int tap = it >> 1;
            float ak = __ldg(wa + tap), pk = __ldg(pa + tap);
#pragma unroll
            for (int mi = 0; mi < 2; mi++)
#pragma unroll
                for (int nq = 0; nq < 4; nq++)
#pragma unroll
                    for (int e = 0; e < 4; e++) {
                        float v = __fdiv_rn(__fmul_rn(psum[mi][nq][e], ak), pk);
                        v = fminf(fmaxf(v, -128.f), 127.f);
                        acc[mi][nq][e] = __fadd_rn(acc[mi][nq][e], __fmul_rn(rintf(v), pk));
                        psum[mi][nq][e] = 0.f;
                    }
        }
        __syncthreads();
    }

    // ---- store pre-BN outputs [n'][o] ----
    float* tout = (LAYER == 1) ? g_t1 : g_t2;
#pragma unroll
    for (int mi = 0; mi < 2; mi++) {
        int row0 = m0 + wm * 32 + mi * 16 + (lane >> 2);
#pragma unroll
        for (int nq = 0; nq < 4; nq++) {
            int col = wn * 32 + nq * 8 + (lane & 3) * 2;
            *reinterpret_cast<float2*>(tout + (size_t)row0 * 128 + col) =
                make_float2(acc[mi][nq][0], acc[mi][nq][1]);
            *reinterpret_cast<float2*>(tout + (size_t)(row0 + 8) * 128 + col) =
                make_float2(acc[mi][nq][2], acc[mi][nq][3]);
        }
    }

    // ---- fused BN stats (interior pixels only) ----
    if (t < 128) { sRed[0][t] = 0.f; sRed[1][t] = 0.f; }
    __syncthreads();
#pragma unroll
    for (int mi = 0; mi < 2; mi++) {
#pragma unroll
        for (int rr = 0; rr < 2; rr++) {
            int np = m0 + wm * 32 + mi * 16 + (lane >> 2) + rr * 8;
            int rp = np % PIMG;
            int hp = rp / 58, wp = rp - hp * 58;
            float msk = ((np < NP) && hp >= 1 && hp <= 56 && wp >= 1 && wp <= 56) ? 1.f : 0.f;
#pragma unroll
            for (int nq = 0; nq < 4; nq++)
#pragma unroll
                for (int e2 = 0; e2 < 2; e2++) {
                    float v = acc[mi][nq][rr * 2 + e2] * msk;
                    float sv = v, qv = v * v;
#pragma unroll
                    for (int d = 4; d <= 16; d <<= 1) {
                        sv += __shfl_xor_sync(0xffffffffu, sv, d);
                        qv += __shfl_xor_sync(0xffffffffu, qv, d);
                    }
                    if (lane < 4) {
                        int col = wn * 32 + nq * 8 + lane * 2 + e2;
                        atomicAdd(&sRed[0][col], sv);
                        atomicAdd(&sRed[1][col], qv);
                    }
                }
        }
    }
    __syncthreads();
    if (t < 128) {
        atomicAdd(((LAYER == 1) ? g_sum1 : g_sum2) + t, sRed[0][t]);
        atomicAdd(((LAYER == 1) ? g_sq1 : g_sq2) + t, sRed[1][t]);
    }
}

// ---------------- final: out = relu(bn2(t2) + x), NCHW ----------------
__global__ void final_kernel(const float* __restrict__ x, float* __restrict__ out)
{
    __shared__ float s[56 * 129];
    int b = blockIdx.x / 56, h = blockIdx.x % 56;
    int np0 = b * PIMG + (h + 1) * 58 + 1;
    for (int i = threadIdx.x; i < 56 * 128; i += 256) {
        int w = i >> 7, c = i & 127;
        s[w * 129 + c] = g_t2[(size_t)(np0 + w) * 128 + c];
    }
    __syncthreads();
    for (int i = threadIdx.x; i < 56 * 128; i += 256) {
        int c = i / 56, w = i - c * 56;
        int e = b * XSTRB + c * HWSZ + h * 56 + w;
        out[e] = fmaxf(fmaf(s[w * 129 + c], g_scale2[c], g_bias2[c]) + __ldg(x + e), 0.f);
    }
}

// ---------------- launch ----------------
extern "C" void kernel_launch(void* const* d_in, const int* in_sizes, int n_in,
                              void* d_out, int out_size)
{
    const float* x   = (const float*)d_in[0];
    const float* w1  = (const float*)d_in[1];
    const float* wa1 = (const float*)d_in[2];
    const float* pa1 = (const float*)d_in[3];
    const float* g1  = (const float*)d_in[4];
    const float* b1  = (const float*)d_in[5];
    const float* w2  = (const float*)d_in[6];
    const float* wa2 = (const float*)d_in[7];
    const float* pa2 = (const float*)d_in[8];
    const float* g2  = (const float*)d_in[9];
    const float* b2  = (const float*)d_in[10];
    float* out = (float*)d_out;
    (void)in_sizes; (void)n_in; (void)out_size;

    cudaFuncSetAttribute(conv_kernel<1>, cudaFuncAttributeMaxDynamicSharedMemorySize, SMEM_CONV);
    cudaFuncSetAttribute(conv_kernel<2>, cudaFuncAttributeMaxDynamicSharedMemorySize, SMEM_CONV);

    prep_kernel<<<1152, 256>>>(w1, wa1, w2, wa2);
    xsplit_kernel<<<936, 256>>>(x);
    conv_kernel<1><<<NT, 512, SMEM_CONV>>>(wa1, pa1);
    bn_finalize_kernel<<<1, 128>>>(1, g1, b1);
    bnsplit_kernel<<<ROWS_BUF / 2, 256>>>();
    conv_kernel<2><<<NT, 512, SMEM_CONV>>>(wa2, pa2);
    bn_finalize_kernel<<<1, 128>>>(2, g2, b2);
    final_kernel<<<896, 256>>>(x, out);
}